// round 8
// baseline (speedup 1.0000x reference)
#include <cuda_runtime.h>
#include <cuda_fp16.h>
#include <math.h>
#include <stdint.h>

// ---------------------------------------------------------------------------
// Swin-style transformer encoder. mma.sync fp16 GEMMs + half2 attention.
// B=8, H=W=64, D=512, NH=16, DK=32, WS=8, SH=4, L=4
// ---------------------------------------------------------------------------

#define BATCH 8
#define HH 64
#define WW 64
#define DIM 512
#define NHEAD 16
#define DKH 32
#define WSZ 8
#define SHF 4
#define NLAYER 4
#define NTOK (BATCH * HH * WW)          // 32768
#define SCALE 0.17677669529663687f     // 1/sqrt(32)

#define WOFF_Q  0
#define WOFF_KV 262144
#define WOFF_O  786432
#define WOFF_W1 1048576
#define WOFF_W2 2097152
#define WLAYER  3145728

// ---------------------------------------------------------------------------
// Scratch
// ---------------------------------------------------------------------------
__device__ __half g_xn  [(size_t)NTOK * DIM];
__device__ __half g_qkv [(size_t)NTOK * 1536];
__device__ __half g_o   [(size_t)NTOK * DIM];
__device__ __half g_m   [(size_t)NTOK * DIM * 4];
__device__ __half g_wt  [(size_t)NLAYER * WLAYER];
__device__ float  g_bqkv[(size_t)NLAYER * 1536];

// ---------------------------------------------------------------------------
// Helpers
// ---------------------------------------------------------------------------
__device__ __forceinline__ uint32_t smem_u32(const void* p) {
    uint32_t a;
    asm("{ .reg .u64 t; cvta.to.shared.u64 t, %1; cvt.u32.u64 %0, t; }"
        : "=r"(a) : "l"(p));
    return a;
}
__device__ __forceinline__ void cpa16(uint32_t dst, const void* src) {
    asm volatile("cp.async.cg.shared.global [%0], [%1], 16;" :: "r"(dst), "l"(src));
}
__device__ __forceinline__ void ldsm_x4(uint32_t* r, uint32_t addr) {
    asm volatile("ldmatrix.sync.aligned.m8n8.x4.shared.b16 {%0,%1,%2,%3}, [%4];"
                 : "=r"(r[0]), "=r"(r[1]), "=r"(r[2]), "=r"(r[3]) : "r"(addr));
}
__device__ __forceinline__ void mma16816(float* d, const uint32_t* a, const uint32_t* b) {
    asm volatile("mma.sync.aligned.m16n8k16.row.col.f32.f16.f16.f32 "
        "{%0,%1,%2,%3}, {%4,%5,%6,%7}, {%8,%9}, {%0,%1,%2,%3};"
        : "+f"(d[0]), "+f"(d[1]), "+f"(d[2]), "+f"(d[3])
        : "r"(a[0]), "r"(a[1]), "r"(a[2]), "r"(a[3]), "r"(b[0]), "r"(b[1]));
}
__device__ __forceinline__ float gelu_tanh(float u) {
    float t = tanhf(0.7978845608028654f * (u + 0.044715f * u * u * u));
    return 0.5f * u * (1.0f + t);
}
__device__ __forceinline__ uint32_t pack_h2(float a, float b) {
    __half2 h = __floats2half2_rn(a, b);
    return *(uint32_t*)&h;
}

// ---------------------------------------------------------------------------
// Weight transform: W[K,N] fp32 -> Wt[N,K] fp16  (blockIdx.z = layer)
// ---------------------------------------------------------------------------
__global__ void wtrans_kernel(const float* __restrict__ W,
                              __half* __restrict__ T,
                              int K, int N)
{
    W += (size_t)blockIdx.z * K * N;
    T += (size_t)blockIdx.z * WLAYER;
    __shared__ float t[32][33];
    int nb = blockIdx.x * 32, kb = blockIdx.y * 32;
    int tx = threadIdx.x & 31, ty = threadIdx.x >> 5;
#pragma unroll
    for (int i = 0; i < 32; i += 8)
        t[ty + i][tx] = W[(size_t)(kb + ty + i) * N + nb + tx];
    __syncthreads();
#pragma unroll
    for (int i = 0; i < 32; i += 8)
        T[(size_t)(nb + ty + i) * K + kb + tx] = __float2half_rn(t[tx][ty + i]);
}

// Bias concat: [bq(512) | bkv(1024)] per layer
__global__ void bcat_kernel(const float* __restrict__ bq,
                            const float* __restrict__ bkv,
                            float* __restrict__ out)
{
    int l = blockIdx.x;
    int t = blockIdx.y * 512 + threadIdx.x;
    out[(size_t)l * 1536 + t] =
        (t < 512) ? bq[(size_t)l * 512 + t] : bkv[(size_t)l * 1024 + t - 512];
}

// ---------------------------------------------------------------------------
// LayerNorm: warp per token (8 tokens / 256-thread block)
// ---------------------------------------------------------------------------
__global__ __launch_bounds__(256)
void ln_kernel(const float* __restrict__ X,
               const float* __restrict__ gam,
               const float* __restrict__ bet,
               __half* __restrict__ Y)
{
    int t  = blockIdx.x * 8 + (threadIdx.x >> 5);
    int ln = threadIdx.x & 31;
    const float4* xr = (const float4*)(X + (size_t)t * DIM);

    float4 v[4];
    float s = 0.0f, s2 = 0.0f;
#pragma unroll
    for (int j = 0; j < 4; j++) {
        v[j] = xr[ln + 32 * j];
        s  += v[j].x + v[j].y + v[j].z + v[j].w;
        s2 += fmaf(v[j].x, v[j].x, fmaf(v[j].y, v[j].y,
              fmaf(v[j].z, v[j].z, v[j].w * v[j].w)));
    }
#pragma unroll
    for (int o = 16; o > 0; o >>= 1) {
        s  += __shfl_xor_sync(0xffffffffu, s,  o);
        s2 += __shfl_xor_sync(0xffffffffu, s2, o);
    }
    float mean = s * (1.0f / DIM);
    float var  = s2 * (1.0f / DIM) - mean * mean;
    float rstd = rsqrtf(var + 1e-5f);

    uint2* yr = (uint2*)(Y + (size_t)t * DIM);
#pragma unroll
    for (int j = 0; j < 4; j++) {
        float4 g4 = ((const float4*)gam)[ln + 32 * j];
        float4 b4 = ((const float4*)bet)[ln + 32 * j];
        float o0 = (v[j].x - mean) * rstd * g4.x + b4.x;
        float o1 = (v[j].y - mean) * rstd * g4.y + b4.y;
        float o2 = (v[j].z - mean) * rstd * g4.z + b4.z;
        float o3 = (v[j].w - mean) * rstd * g4.w + b4.w;
        yr[ln + 32 * j] = make_uint2(pack_h2(o0, o1), pack_h2(o2, o3));
    }
}

// ---------------------------------------------------------------------------
// mma.sync GEMM: C[M,N] = epi(A[M,K] @ B[N,K]^T + bias)
// Tile 256x128x32, 8 warps (4x2, each 64x64), 3-stage cp.async, fp16.
// EPI: 1 = bias+gelu->fp16   2 = bias+res->fp32   3 = bias->fp16
// smem per stage: A 16K | B 8K = 24KB.  3 stages + 512B bias.
// Swizzle: 16B seg s of row r stored at seg (s ^ ((r>>1)&3)).
// ---------------------------------------------------------------------------
#define MG_STAGE 24576
#define MG_SMEM  (3 * MG_STAGE + 512)

__device__ __forceinline__ void mg_load_chunk(
    uint32_t st,
    const __half* __restrict__ A, const __half* __restrict__ B,
    int bm, int bn, int K, int k0, int tid)
{
    // A: 256 rows x 4 segs = 1024 cp (4/thread)
#pragma unroll
    for (int i = 0; i < 4; i++) {
        int ch = tid + (i << 8);
        int r  = ch >> 2;
        int s  = ch & 3;
        uint32_t off = (uint32_t)(r * 64) + (uint32_t)((s ^ ((r >> 1) & 3)) << 4);
        cpa16(st + off, A + (size_t)(bm + r) * K + k0 + s * 8);
    }
    // B: 128 rows x 4 segs = 512 cp (2/thread)
#pragma unroll
    for (int i = 0; i < 2; i++) {
        int ch = tid + (i << 8);
        int r  = ch >> 2;
        int s  = ch & 3;
        uint32_t off = (uint32_t)(r * 64) + (uint32_t)((s ^ ((r >> 1) & 3)) << 4);
        cpa16(st + 16384 + off, B + (size_t)(bn + r) * K + k0 + s * 8);
    }
}

template<int EPI>
__global__ __launch_bounds__(256, 1)
void mg_gemm(const __half* __restrict__ A, const __half* __restrict__ B,
             const float* __restrict__ bias, const float* __restrict__ res,
             float* __restrict__ outF, __half* __restrict__ outH,
             int M, int N, int K)
{
    extern __shared__ __align__(1024) char smem[];
    const int tid  = threadIdx.x;
    const int lane = tid & 31;
    const int wid  = tid >> 5;
    const int wm   = wid & 3;          // m offset 64*wm
    const int wn   = wid >> 2;         // n offset 64*wn
    const int bm = blockIdx.y * 256, bn = blockIdx.x * 128;

    float* sbias = (float*)(smem + 3 * MG_STAGE);
    if (tid < 32)
        ((float4*)sbias)[tid] = ((const float4*)(bias + bn))[tid];

    uint32_t sb = smem_u32(smem);

    float acc[4][8][4];
#pragma unroll
    for (int mi = 0; mi < 4; mi++)
#pragma unroll
        for (int ni = 0; ni < 8; ni++)
#pragma unroll
            for (int j = 0; j < 4; j++) acc[mi][ni][j] = 0.0f;

    const int nch = K >> 5;

    mg_load_chunk(sb, A, B, bm, bn, K, 0, tid);
    asm volatile("cp.async.commit_group;");
    if (nch > 1)
        mg_load_chunk(sb + MG_STAGE, A, B, bm, bn, K, 32, tid);
    asm volatile("cp.async.commit_group;");

    const int j8 = lane & 7;
    const int a_row_off = wm * 64 + j8 + ((lane >> 3) & 1) * 8;
    const int a_seg_off = (lane >> 4);
    const int b_row_off = wn * 64 + j8 + ((lane >> 4) & 1) * 8;
    const int b_seg_off = ((lane >> 3) & 1);

    for (int c = 0; c < nch; c++) {
        asm volatile("cp.async.wait_group 1;");
        __syncthreads();

        if (c + 2 < nch)
            mg_load_chunk(sb + (uint32_t)((c + 2) % 3) * MG_STAGE,
                          A, B, bm, bn, K, (c + 2) << 5, tid);
        asm volatile("cp.async.commit_group;");

        uint32_t st = sb + (uint32_t)(c % 3) * MG_STAGE;

#pragma unroll
        for (int kk = 0; kk < 2; kk++) {
            uint32_t a_f[4][4];
#pragma unroll
            for (int mi = 0; mi < 4; mi++) {
                int row = a_row_off + mi * 16;
                int seg = kk * 2 + a_seg_off;
                uint32_t off = (uint32_t)(row * 64) +
                               (uint32_t)((seg ^ ((row >> 1) & 3)) << 4);
                ldsm_x4(a_f[mi], st + off);
            }
            uint32_t b_f[4][4];
#pragma unroll
            for (int pi = 0; pi < 4; pi++) {
                int row = b_row_off + pi * 16;
                int seg = kk * 2 + b_seg_off;
                uint32_t off = (uint32_t)(row * 64) +
                               (uint32_t)((seg ^ ((row >> 1) & 3)) << 4);
                ldsm_x4(b_f[pi], st + 16384 + off);
            }
#pragma unroll
            for (int mi = 0; mi < 4; mi++)
#pragma unroll
                for (int ni = 0; ni < 8; ni++)
                    mma16816(acc[mi][ni], a_f[mi], &b_f[ni >> 1][(ni & 1) * 2]);
        }
    }
    __syncthreads();

#pragma unroll
    for (int mi = 0; mi < 4; mi++) {
        int r0 = bm + wm * 64 + mi * 16 + (lane >> 2);
#pragma unroll
        for (int ni = 0; ni < 8; ni++) {
            int cb = wn * 64 + ni * 8 + 2 * (lane & 3);
            float bv0 = sbias[cb], bv1 = sbias[cb + 1];
            float v0 = acc[mi][ni][0] + bv0;
            float v1 = acc[mi][ni][1] + bv1;
            float v2 = acc[mi][ni][2] + bv0;
            float v3 = acc[mi][ni][3] + bv1;
            size_t g0 = (size_t)r0 * N + bn + cb;
            size_t g1 = (size_t)(r0 + 8) * N + bn + cb;
            if (EPI == 2) {
                float2 q0 = *(const float2*)(res + g0);
                float2 q1 = *(const float2*)(res + g1);
                *(float2*)(outF + g0) = make_float2(v0 + q0.x, v1 + q0.y);
                *(float2*)(outF + g1) = make_float2(v2 + q1.x, v3 + q1.y);
            } else if (EPI == 3) {
                *(uint32_t*)(outH + g0) = pack_h2(v0, v1);
                *(uint32_t*)(outH + g1) = pack_h2(v2, v3);
            } else {
                v0 = gelu_tanh(v0); v1 = gelu_tanh(v1);
                v2 = gelu_tanh(v2); v3 = gelu_tanh(v3);
                *(uint32_t*)(outH + g0) = pack_h2(v0, v1);
                *(uint32_t*)(outH + g1) = pack_h2(v2, v3);
            }
        }
    }
}

// ---------------------------------------------------------------------------
// Windowed attention. Reads packed QKV [NTOK,1536] (q|k|v), writes fp16 O.
// Thread t: rows {t>>3, (t>>3)+32}, cols {(t&7)+8c | c=0..7}.
// ---------------------------------------------------------------------------
__global__ __launch_bounds__(256)
void attn_kernel(const __half* __restrict__ QKV,
                 const int*   __restrict__ relIdx,
                 const float* __restrict__ table,
                 __half* __restrict__ O)
{
    __shared__ __half2 sQ[64][20];
    __shared__ __half2 sK[64][20];
    __shared__ __half2 sV[64][20];
    __shared__ float   sA[64][65];
    __shared__ int     sTok[64];
    __shared__ int     sLab[64];
    __shared__ float   sTab[225];

    int h   = blockIdx.x;
    int win = blockIdx.y;
    int b   = blockIdx.z;
    int nwh = win >> 3, nww = win & 7;
    int tid = threadIdx.x;

    if (tid < 64) {
        int i = tid >> 3, j = tid & 7;
        int gh = (nwh * WSZ + i + SHF) & (HH - 1);
        int gw = (nww * WSZ + j + SHF) & (WW - 1);
        sTok[tid] = ((b * HH + gh) << 6) + gw;
        int ih = nwh * WSZ + i, iw = nww * WSZ + j;
        int rh = (ih >= HH - WSZ) + (ih >= HH - SHF);
        int rw = (iw >= WW - WSZ) + (iw >= WW - SHF);
        sLab[tid] = rh * 3 + rw;
    }
    if (tid < 225) sTab[tid] = table[tid * NHEAD + h];
    __syncthreads();

    {
        int r  = tid >> 2;
        int sg = tid & 3;
        size_t base = (size_t)sTok[r] * 1536 + h * DKH + sg * 8;
        *(uint4*)&sQ[r][sg * 4] = *(const uint4*)(QKV + base);
        *(uint4*)&sK[r][sg * 4] = *(const uint4*)(QKV + base + 512);
        *(uint4*)&sV[r][sg * 4] = *(const uint4*)(QKV + base + 1024);
    }
    __syncthreads();

    const int r0 = tid >> 3;
    const int cl = tid & 7;

    {
        float2 q0[16], q1[16];
#pragma unroll
        for (int d = 0; d < 16; d++) {
            q0[d] = __half22float2(sQ[r0][d]);
            q1[d] = __half22float2(sQ[r0 + 32][d]);
        }
        int lab0 = sLab[r0], lab1 = sLab[r0 + 32];
        float sc0[8], sc1[8];
#pragma unroll
        for (int c = 0; c < 8; c++) {
            int col = cl + (c << 3);
            float a0 = 0.0f, a1 = 0.0f;
#pragma unroll
            for (int d = 0; d < 16; d++) {
                float2 k2 = __half22float2(sK[col][d]);
                a0 = fmaf(q0[d].x, k2.x, a0);
                a0 = fmaf(q0[d].y, k2.y, a0);
                a1 = fmaf(q1[d].x, k2.x, a1);
                a1 = fmaf(q1[d].y, k2.y, a1);
            }
            int lc = sLab[col];
            float bi0 = sTab[relIdx[r0 * 64 + col]];
            float bi1 = sTab[relIdx[(r0 + 32) * 64 + col]];
            a0 = a0 * SCALE + bi0;
            a1 = a1 * SCALE + bi1;
            if (lab0 != lc) a0 = -1e9f;
            if (lab1 != lc) a1 = -1e9f;
            sc0[c] = a0; sc1[c] = a1;
        }
        float m0 = sc0[0], m1 = sc1[0];
#pragma unroll
        for (int c = 1; c < 8; c++) { m0 = fmaxf(m0, sc0[c]); m1 = fmaxf(m1, sc1[c]); }
#pragma unroll
        for (int o = 1; o < 8; o <<= 1) {
            m0 = fmaxf(m0, __shfl_xor_sync(0xffffffffu, m0, o));
            m1 = fmaxf(m1, __shfl_xor_sync(0xffffffffu, m1, o));
        }
        float s0 = 0.0f, s1 = 0.0f;
#pragma unroll
        for (int c = 0; c < 8; c++) {
            sc0[c] = __expf(sc0[c] - m0); s0 += sc0[c];
            sc1[c] = __expf(sc1[c] - m1); s1 += sc1[c];
        }
#pragma unroll
        for (int o = 1; o < 8; o <<= 1) {
            s0 += __shfl_xor_sync(0xffffffffu, s0, o);
            s1 += __shfl_xor_sync(0xffffffffu, s1, o);
        }
        float i0 = 1.0f / s0, i1 = 1.0f / s1;
#pragma unroll
        for (int c = 0; c < 8; c++) {
            int col = cl + (c << 3);
            sA[r0][col]      = sc0[c] * i0;
            sA[r0 + 32][col] = sc1[c] * i1;
        }
    }
    __syncthreads();

    {
        const int dh = (tid & 7) * 2;
        float o00 = 0, o01 = 0, o02 = 0, o03 = 0;
        float o10 = 0, o11 = 0, o12 = 0, o13 = 0;
#pragma unroll
        for (int k = 0; k < 64; k++) {
            float a0 = sA[r0][k];
            float a1 = sA[r0 + 32][k];
            uint2 vv = *(uint2*)&sV[k][dh];
            float2 v0 = __half22float2(*(__half2*)&vv.x);
            float2 v1 = __half22float2(*(__half2*)&vv.y);
            o00 = fmaf(a0, v0.x, o00); o01 = fmaf(a0, v0.y, o01);
            o02 = fmaf(a0, v1.x, o02); o03 = fmaf(a0, v1.y, o03);
            o10 = fmaf(a1, v0.x, o10); o11 = fmaf(a1, v0.y, o11);
            o12 = fmaf(a1, v1.x, o12); o13 = fmaf(a1, v1.y, o13);
        }
        size_t b0 = (size_t)sTok[r0] * DIM + h * DKH + dh * 2;
        *(uint2*)(O + b0) = make_uint2(pack_h2(o00, o01), pack_h2(o02, o03));
        size_t b1 = (size_t)sTok[r0 + 32] * DIM + h * DKH + dh * 2;
        *(uint2*)(O + b1) = make_uint2(pack_h2(o10, o11), pack_h2(o12, o13));
    }
}

// ---------------------------------------------------------------------------
// Launch
// ---------------------------------------------------------------------------
extern "C" void kernel_launch(void* const* d_in, const int* in_sizes, int n_in,
                              void* d_out, int out_size)
{
    const float* x_in      = (const float*)d_in[0];
    const int*   rel_index = (const int*)  d_in[2];
    const float* Wq        = (const float*)d_in[3];
    const float* bq        = (const float*)d_in[4];
    const float* Wkv       = (const float*)d_in[5];
    const float* bkv       = (const float*)d_in[6];
    const float* Wo        = (const float*)d_in[7];
    const float* bo        = (const float*)d_in[8];
    const float* rel_table = (const float*)d_in[9];
    const float* ln1_g     = (const float*)d_in[10];
    const float* ln1_b     = (const float*)d_in[11];
    const float* ln2_g     = (const float*)d_in[12];
    const float* ln2_b     = (const float*)d_in[13];
    const float* W1        = (const float*)d_in[14];
    const float* b1        = (const float*)d_in[15];
    const float* W2        = (const float*)d_in[16];
    const float* b2        = (const float*)d_in[17];

    float* xbuf = (float*)d_out;

    __half *xn, *qkv, *o, *m, *wt;
    float *bqkv;
    cudaGetSymbolAddress((void**)&xn,   g_xn);
    cudaGetSymbolAddress((void**)&qkv,  g_qkv);
    cudaGetSymbolAddress((void**)&o,    g_o);
    cudaGetSymbolAddress((void**)&m,    g_m);
    cudaGetSymbolAddress((void**)&wt,   g_wt);
    cudaGetSymbolAddress((void**)&bqkv, g_bqkv);

    cudaFuncSetAttribute(mg_gemm<1>, cudaFuncAttributeMaxDynamicSharedMemorySize, MG_SMEM);
    cudaFuncSetAttribute(mg_gemm<2>, cudaFuncAttributeMaxDynamicSharedMemorySize, MG_SMEM);
    cudaFuncSetAttribute(mg_gemm<3>, cudaFuncAttributeMaxDynamicSharedMemorySize, MG_SMEM);

    cudaMemcpyAsync(xbuf, x_in, (size_t)NTOK * DIM * sizeof(float),
                    cudaMemcpyDeviceToDevice);

    // Weight transform, all layers batched via blockIdx.z
    wtrans_kernel<<<dim3(16, 16, NLAYER), 256>>>(Wq,  wt + WOFF_Q,  512, 512);
    wtrans_kernel<<<dim3(32, 16, NLAYER), 256>>>(Wkv, wt + WOFF_KV, 512, 1024);
    wtrans_kernel<<<dim3(16, 16, NLAYER), 256>>>(Wo,  wt + WOFF_O,  512, 512);
    wtrans_kernel<<<dim3(64, 16, NLAYER), 256>>>(W1,  wt + WOFF_W1, 512, 2048);
    wtrans_kernel<<<dim3(16, 64, NLAYER), 256>>>(W2,  wt + WOFF_W2, 2048, 512);
    bcat_kernel<<<dim3(NLAYER, 3), 512>>>(bq, bkv, bqkv);

    dim3 gLN(NTOK / 8), bLN(256);
    dim3 gAttn(NHEAD, 64, BATCH), bAttn(256);

    for (int l = 0; l < NLAYER; l++) {
        size_t lw = (size_t)l * WLAYER;
        const float* bov  = bo  + (size_t)l * DIM;
        const float* tab  = rel_table + (size_t)l * 225 * NHEAD;
        const float* b1v  = b1  + (size_t)l * 4 * DIM;
        const float* b2v  = b2  + (size_t)l * DIM;

        ln_kernel<<<gLN, bLN>>>(xbuf, ln1_g + (size_t)l*DIM, ln1_b + (size_t)l*DIM, xn);
        // Fused Q+KV GEMM: N=1536 over adjacent [Wq|Wkv] transposed block
        mg_gemm<3><<<dim3(12, 128), 256, MG_SMEM>>>(
            xn, wt + lw + WOFF_Q, bqkv + (size_t)l * 1536, nullptr,
            nullptr, qkv, NTOK, 1536, 512);
        attn_kernel<<<gAttn, bAttn>>>(qkv, rel_index, tab, o);
        mg_gemm<2><<<dim3(4, 128), 256, MG_SMEM>>>(
            o, wt + lw + WOFF_O, bov, xbuf, xbuf, nullptr, NTOK, 512, 512);
        ln_kernel<<<gLN, bLN>>>(xbuf, ln2_g + (size_t)l*DIM, ln2_b + (size_t)l*DIM, xn);
        mg_gemm<1><<<dim3(16, 128), 256, MG_SMEM>>>(
            xn, wt + lw + WOFF_W1, b1v, nullptr, nullptr, m, NTOK, 2048, 512);
        mg_gemm<2><<<dim3(4, 128), 256, MG_SMEM>>>(
            m, wt + lw + WOFF_W2, b2v, xbuf, xbuf, nullptr, NTOK, 512, 2048);
    }
}

// round 10
// speedup vs baseline: 1.1480x; 1.1480x over previous
#include <cuda_runtime.h>
#include <cuda_fp16.h>
#include <math.h>
#include <stdint.h>

// ---------------------------------------------------------------------------
// Swin-style transformer encoder. mma.sync fp16 GEMMs + half2 attention.
// B=8, H=W=64, D=512, NH=16, DK=32, WS=8, SH=4, L=4
// R9: GEMM core = R7-proven 128x128x32 @ 2 CTA/SM; keep R8's fused QKV.
// ---------------------------------------------------------------------------

#define BATCH 8
#define HH 64
#define WW 64
#define DIM 512
#define NHEAD 16
#define DKH 32
#define WSZ 8
#define SHF 4
#define NLAYER 4
#define NTOK (BATCH * HH * WW)          // 32768
#define SCALE 0.17677669529663687f     // 1/sqrt(32)

#define WOFF_Q  0
#define WOFF_KV 262144
#define WOFF_O  786432
#define WOFF_W1 1048576
#define WOFF_W2 2097152
#define WLAYER  3145728

// ---------------------------------------------------------------------------
// Scratch
// ---------------------------------------------------------------------------
__device__ __half g_xn  [(size_t)NTOK * DIM];
__device__ __half g_qkv [(size_t)NTOK * 1536];
__device__ __half g_o   [(size_t)NTOK * DIM];
__device__ __half g_m   [(size_t)NTOK * DIM * 4];
__device__ __half g_wt  [(size_t)NLAYER * WLAYER];
__device__ float  g_bqkv[(size_t)NLAYER * 1536];

// ---------------------------------------------------------------------------
// Helpers
// ---------------------------------------------------------------------------
__device__ __forceinline__ uint32_t smem_u32(const void* p) {
    uint32_t a;
    asm("{ .reg .u64 t; cvta.to.shared.u64 t, %1; cvt.u32.u64 %0, t; }"
        : "=r"(a) : "l"(p));
    return a;
}
__device__ __forceinline__ void cpa16(uint32_t dst, const void* src) {
    asm volatile("cp.async.cg.shared.global [%0], [%1], 16;" :: "r"(dst), "l"(src));
}
__device__ __forceinline__ void ldsm_x4(uint32_t* r, uint32_t addr) {
    asm volatile("ldmatrix.sync.aligned.m8n8.x4.shared.b16 {%0,%1,%2,%3}, [%4];"
                 : "=r"(r[0]), "=r"(r[1]), "=r"(r[2]), "=r"(r[3]) : "r"(addr));
}
__device__ __forceinline__ void mma16816(float* d, const uint32_t* a, const uint32_t* b) {
    asm volatile("mma.sync.aligned.m16n8k16.row.col.f32.f16.f16.f32 "
        "{%0,%1,%2,%3}, {%4,%5,%6,%7}, {%8,%9}, {%0,%1,%2,%3};"
        : "+f"(d[0]), "+f"(d[1]), "+f"(d[2]), "+f"(d[3])
        : "r"(a[0]), "r"(a[1]), "r"(a[2]), "r"(a[3]), "r"(b[0]), "r"(b[1]));
}
__device__ __forceinline__ float gelu_tanh(float u) {
    float t = tanhf(0.7978845608028654f * (u + 0.044715f * u * u * u));
    return 0.5f * u * (1.0f + t);
}
__device__ __forceinline__ uint32_t pack_h2(float a, float b) {
    __half2 h = __floats2half2_rn(a, b);
    return *(uint32_t*)&h;
}

// ---------------------------------------------------------------------------
// Weight transform: W[K,N] fp32 -> Wt[N,K] fp16  (blockIdx.z = layer)
// ---------------------------------------------------------------------------
__global__ void wtrans_kernel(const float* __restrict__ W,
                              __half* __restrict__ T,
                              int K, int N)
{
    W += (size_t)blockIdx.z * K * N;
    T += (size_t)blockIdx.z * WLAYER;
    __shared__ float t[32][33];
    int nb = blockIdx.x * 32, kb = blockIdx.y * 32;
    int tx = threadIdx.x & 31, ty = threadIdx.x >> 5;
#pragma unroll
    for (int i = 0; i < 32; i += 8)
        t[ty + i][tx] = W[(size_t)(kb + ty + i) * N + nb + tx];
    __syncthreads();
#pragma unroll
    for (int i = 0; i < 32; i += 8)
        T[(size_t)(nb + ty + i) * K + kb + tx] = __float2half_rn(t[tx][ty + i]);
}

// Bias concat: [bq(512) | bkv(1024)] per layer
__global__ void bcat_kernel(const float* __restrict__ bq,
                            const float* __restrict__ bkv,
                            float* __restrict__ out)
{
    int l = blockIdx.x;
    int t = blockIdx.y * 512 + threadIdx.x;
    out[(size_t)l * 1536 + t] =
        (t < 512) ? bq[(size_t)l * 512 + t] : bkv[(size_t)l * 1024 + t - 512];
}

// ---------------------------------------------------------------------------
// LayerNorm: warp per token (8 tokens / 256-thread block)
// ---------------------------------------------------------------------------
__global__ __launch_bounds__(256)
void ln_kernel(const float* __restrict__ X,
               const float* __restrict__ gam,
               const float* __restrict__ bet,
               __half* __restrict__ Y)
{
    int t  = blockIdx.x * 8 + (threadIdx.x >> 5);
    int ln = threadIdx.x & 31;
    const float4* xr = (const float4*)(X + (size_t)t * DIM);

    float4 v[4];
    float s = 0.0f, s2 = 0.0f;
#pragma unroll
    for (int j = 0; j < 4; j++) {
        v[j] = xr[ln + 32 * j];
        s  += v[j].x + v[j].y + v[j].z + v[j].w;
        s2 += fmaf(v[j].x, v[j].x, fmaf(v[j].y, v[j].y,
              fmaf(v[j].z, v[j].z, v[j].w * v[j].w)));
    }
#pragma unroll
    for (int o = 16; o > 0; o >>= 1) {
        s  += __shfl_xor_sync(0xffffffffu, s,  o);
        s2 += __shfl_xor_sync(0xffffffffu, s2, o);
    }
    float mean = s * (1.0f / DIM);
    float var  = s2 * (1.0f / DIM) - mean * mean;
    float rstd = rsqrtf(var + 1e-5f);

    uint2* yr = (uint2*)(Y + (size_t)t * DIM);
#pragma unroll
    for (int j = 0; j < 4; j++) {
        float4 g4 = ((const float4*)gam)[ln + 32 * j];
        float4 b4 = ((const float4*)bet)[ln + 32 * j];
        float o0 = (v[j].x - mean) * rstd * g4.x + b4.x;
        float o1 = (v[j].y - mean) * rstd * g4.y + b4.y;
        float o2 = (v[j].z - mean) * rstd * g4.z + b4.z;
        float o3 = (v[j].w - mean) * rstd * g4.w + b4.w;
        yr[ln + 32 * j] = make_uint2(pack_h2(o0, o1), pack_h2(o2, o3));
    }
}

// ---------------------------------------------------------------------------
// mma.sync GEMM: C[M,N] = epi(A[M,K] @ B[N,K]^T + bias)
// Tile 128x128x32, 8 warps (4x2), 3-stage cp.async, fp16, 2 CTA/SM.
// EPI: 1 = bias+gelu->fp16   2 = bias+res->fp32   3 = bias->fp16
// ---------------------------------------------------------------------------
#define MG_STAGE 16384
#define MG_SMEM  (3 * MG_STAGE + 512)

__device__ __forceinline__ void mg_load_chunk(
    uint32_t st,
    const __half* __restrict__ A, const __half* __restrict__ B,
    int bm, int bn, int K, int k0, int tid)
{
#pragma unroll
    for (int i = 0; i < 2; i++) {
        int ch = tid + (i << 8);
        int r  = ch >> 2;
        int s  = ch & 3;
        uint32_t off = (uint32_t)(r * 64) + (uint32_t)((s ^ ((r >> 1) & 3)) << 4);
        cpa16(st + off,        A + (size_t)(bm + r) * K + k0 + s * 8);
        cpa16(st + 8192 + off, B + (size_t)(bn + r) * K + k0 + s * 8);
    }
}

template<int EPI>
__global__ __launch_bounds__(256, 2)
void mg_gemm(const __half* __restrict__ A, const __half* __restrict__ B,
             const float* __restrict__ bias, const float* __restrict__ res,
             float* __restrict__ outF, __half* __restrict__ outH,
             int M, int N, int K)
{
    extern __shared__ __align__(1024) char smem[];
    const int tid  = threadIdx.x;
    const int lane = tid & 31;
    const int wid  = tid >> 5;
    const int wm   = wid & 3;
    const int wn   = wid >> 2;
    const int bm = blockIdx.y * 128, bn = blockIdx.x * 128;

    float* sbias = (float*)(smem + 3 * MG_STAGE);
    if (tid < 32)
        ((float4*)sbias)[tid] = ((const float4*)(bias + bn))[tid];

    uint32_t sb = smem_u32(smem);

    float acc[2][8][4];
#pragma unroll
    for (int mi = 0; mi < 2; mi++)
#pragma unroll
        for (int ni = 0; ni < 8; ni++)
#pragma unroll
            for (int j = 0; j < 4; j++) acc[mi][ni][j] = 0.0f;

    const int nch = K >> 5;

    mg_load_chunk(sb, A, B, bm, bn, K, 0, tid);
    asm volatile("cp.async.commit_group;");
    if (nch > 1)
        mg_load_chunk(sb + MG_STAGE, A, B, bm, bn, K, 32, tid);
    asm volatile("cp.async.commit_group;");

    const int j8 = lane & 7;
    const int a_row_off = wm * 32 + j8 + ((lane >> 3) & 1) * 8;
    const int a_seg_off = (lane >> 4);
    const int b_row_off = wn * 64 + j8 + ((lane >> 4) & 1) * 8;
    const int b_seg_off = ((lane >> 3) & 1);

    for (int c = 0; c < nch; c++) {
        asm volatile("cp.async.wait_group 1;");
        __syncthreads();

        if (c + 2 < nch)
            mg_load_chunk(sb + (uint32_t)((c + 2) % 3) * MG_STAGE,
                          A, B, bm, bn, K, (c + 2) << 5, tid);
        asm volatile("cp.async.commit_group;");

        uint32_t st = sb + (uint32_t)(c % 3) * MG_STAGE;

#pragma unroll
        for (int kk = 0; kk < 2; kk++) {
            uint32_t a_f[2][4];
#pragma unroll
            for (int mi = 0; mi < 2; mi++) {
                int row = a_row_off + mi * 16;
                int seg = kk * 2 + a_seg_off;
                uint32_t off = (uint32_t)(row * 64) +
                               (uint32_t)((seg ^ ((row >> 1) & 3)) << 4);
                ldsm_x4(a_f[mi], st + off);
            }
            uint32_t b_f[4][4];
#pragma unroll
            for (int pi = 0; pi < 4; pi++) {
                int row = b_row_off + pi * 16;
                int seg = kk * 2 + b_seg_off;
                uint32_t off = (uint32_t)(row * 64) +
                               (uint32_t)((seg ^ ((row >> 1) & 3)) << 4);
                ldsm_x4(b_f[pi], st + 8192 + off);
            }
#pragma unroll
            for (int mi = 0; mi < 2; mi++)
#pragma unroll
                for (int ni = 0; ni < 8; ni++)
                    mma16816(acc[mi][ni], a_f[mi], &b_f[ni >> 1][(ni & 1) * 2]);
        }
    }
    __syncthreads();

#pragma unroll
    for (int mi = 0; mi < 2; mi++) {
        int r0 = bm + wm * 32 + mi * 16 + (lane >> 2);
#pragma unroll
        for (int ni = 0; ni < 8; ni++) {
            int cb = wn * 64 + ni * 8 + 2 * (lane & 3);
            float bv0 = sbias[cb], bv1 = sbias[cb + 1];
            float v0 = acc[mi][ni][0] + bv0;
            float v1 = acc[mi][ni][1] + bv1;
            float v2 = acc[mi][ni][2] + bv0;
            float v3 = acc[mi][ni][3] + bv1;
            size_t g0 = (size_t)r0 * N + bn + cb;
            size_t g1 = (size_t)(r0 + 8) * N + bn + cb;
            if (EPI == 2) {
                float2 q0 = *(const float2*)(res + g0);
                float2 q1 = *(const float2*)(res + g1);
                *(float2*)(outF + g0) = make_float2(v0 + q0.x, v1 + q0.y);
                *(float2*)(outF + g1) = make_float2(v2 + q1.x, v3 + q1.y);
            } else if (EPI == 3) {
                *(uint32_t*)(outH + g0) = pack_h2(v0, v1);
                *(uint32_t*)(outH + g1) = pack_h2(v2, v3);
            } else {
                v0 = gelu_tanh(v0); v1 = gelu_tanh(v1);
                v2 = gelu_tanh(v2); v3 = gelu_tanh(v3);
                *(uint32_t*)(outH + g0) = pack_h2(v0, v1);
                *(uint32_t*)(outH + g1) = pack_h2(v2, v3);
            }
        }
    }
}

// ---------------------------------------------------------------------------
// Windowed attention. Reads packed QKV [NTOK,1536] (q|k|v), writes fp16 O.
// ---------------------------------------------------------------------------
__global__ __launch_bounds__(256)
void attn_kernel(const __half* __restrict__ QKV,
                 const int*   __restrict__ relIdx,
                 const float* __restrict__ table,
                 __half* __restrict__ O)
{
    __shared__ __half2 sQ[64][20];
    __shared__ __half2 sK[64][20];
    __shared__ __half2 sV[64][20];
    __shared__ float   sA[64][65];
    __shared__ int     sTok[64];
    __shared__ int     sLab[64];
    __shared__ float   sTab[225];

    int h   = blockIdx.x;
    int win = blockIdx.y;
    int b   = blockIdx.z;
    int nwh = win >> 3, nww = win & 7;
    int tid = threadIdx.x;

    if (tid < 64) {
        int i = tid >> 3, j = tid & 7;
        int gh = (nwh * WSZ + i + SHF) & (HH - 1);
        int gw = (nww * WSZ + j + SHF) & (WW - 1);
        sTok[tid] = ((b * HH + gh) << 6) + gw;
        int ih = nwh * WSZ + i, iw = nww * WSZ + j;
        int rh = (ih >= HH - WSZ) + (ih >= HH - SHF);
        int rw = (iw >= WW - WSZ) + (iw >= WW - SHF);
        sLab[tid] = rh * 3 + rw;
    }
    if (tid < 225) sTab[tid] = table[tid * NHEAD + h];
    __syncthreads();

    {
        int r  = tid >> 2;
        int sg = tid & 3;
        size_t base = (size_t)sTok[r] * 1536 + h * DKH + sg * 8;
        *(uint4*)&sQ[r][sg * 4] = *(const uint4*)(QKV + base);
        *(uint4*)&sK[r][sg * 4] = *(const uint4*)(QKV + base + 512);
        *(uint4*)&sV[r][sg * 4] = *(const uint4*)(QKV + base + 1024);
    }
    __syncthreads();

    const int r0 = tid >> 3;
    const int cl = tid & 7;

    {
        float2 q0[16], q1[16];
#pragma unroll
        for (int d = 0; d < 16; d++) {
            q0[d] = __half22float2(sQ[r0][d]);
            q1[d] = __half22float2(sQ[r0 + 32][d]);
        }
        int lab0 = sLab[r0], lab1 = sLab[r0 + 32];
        float sc0[8], sc1[8];
#pragma unroll
        for (int c = 0; c < 8; c++) {
            int col = cl + (c << 3);
            float a0 = 0.0f, a1 = 0.0f;
#pragma unroll
            for (int d = 0; d < 16; d++) {
                float2 k2 = __half22float2(sK[col][d]);
                a0 = fmaf(q0[d].x, k2.x, a0);
                a0 = fmaf(q0[d].y, k2.y, a0);
                a1 = fmaf(q1[d].x, k2.x, a1);
                a1 = fmaf(q1[d].y, k2.y, a1);
            }
            int lc = sLab[col];
            float bi0 = sTab[relIdx[r0 * 64 + col]];
            float bi1 = sTab[relIdx[(r0 + 32) * 64 + col]];
            a0 = a0 * SCALE + bi0;
            a1 = a1 * SCALE + bi1;
            if (lab0 != lc) a0 = -1e9f;
            if (lab1 != lc) a1 = -1e9f;
            sc0[c] = a0; sc1[c] = a1;
        }
        float m0 = sc0[0], m1 = sc1[0];
#pragma unroll
        for (int c = 1; c < 8; c++) { m0 = fmaxf(m0, sc0[c]); m1 = fmaxf(m1, sc1[c]); }
#pragma unroll
        for (int o = 1; o < 8; o <<= 1) {
            m0 = fmaxf(m0, __shfl_xor_sync(0xffffffffu, m0, o));
            m1 = fmaxf(m1, __shfl_xor_sync(0xffffffffu, m1, o));
        }
        float s0 = 0.0f, s1 = 0.0f;
#pragma unroll
        for (int c = 0; c < 8; c++) {
            sc0[c] = __expf(sc0[c] - m0); s0 += sc0[c];
            sc1[c] = __expf(sc1[c] - m1); s1 += sc1[c];
        }
#pragma unroll
        for (int o = 1; o < 8; o <<= 1) {
            s0 += __shfl_xor_sync(0xffffffffu, s0, o);
            s1 += __shfl_xor_sync(0xffffffffu, s1, o);
        }
        float i0 = 1.0f / s0, i1 = 1.0f / s1;
#pragma unroll
        for (int c = 0; c < 8; c++) {
            int col = cl + (c << 3);
            sA[r0][col]      = sc0[c] * i0;
            sA[r0 + 32][col] = sc1[c] * i1;
        }
    }
    __syncthreads();

    {
        const int dh = (tid & 7) * 2;
        float o00 = 0, o01 = 0, o02 = 0, o03 = 0;
        float o10 = 0, o11 = 0, o12 = 0, o13 = 0;
#pragma unroll
        for (int k = 0; k < 64; k++) {
            float a0 = sA[r0][k];
            float a1 = sA[r0 + 32][k];
            uint2 vv = *(uint2*)&sV[k][dh];
            float2 v0 = __half22float2(*(__half2*)&vv.x);
            float2 v1 = __half22float2(*(__half2*)&vv.y);
            o00 = fmaf(a0, v0.x, o00); o01 = fmaf(a0, v0.y, o01);
            o02 = fmaf(a0, v1.x, o02); o03 = fmaf(a0, v1.y, o03);
            o10 = fmaf(a1, v0.x, o10); o11 = fmaf(a1, v0.y, o11);
            o12 = fmaf(a1, v1.x, o12); o13 = fmaf(a1, v1.y, o13);
        }
        size_t b0 = (size_t)sTok[r0] * DIM + h * DKH + dh * 2;
        *(uint2*)(O + b0) = make_uint2(pack_h2(o00, o01), pack_h2(o02, o03));
        size_t b1 = (size_t)sTok[r0 + 32] * DIM + h * DKH + dh * 2;
        *(uint2*)(O + b1) = make_uint2(pack_h2(o10, o11), pack_h2(o12, o13));
    }
}

// ---------------------------------------------------------------------------
// Launch
// ---------------------------------------------------------------------------
extern "C" void kernel_launch(void* const* d_in, const int* in_sizes, int n_in,
                              void* d_out, int out_size)
{
    const float* x_in      = (const float*)d_in[0];
    const int*   rel_index = (const int*)  d_in[2];
    const float* Wq        = (const float*)d_in[3];
    const float* bq        = (const float*)d_in[4];
    const float* Wkv       = (const float*)d_in[5];
    const float* bkv       = (const float*)d_in[6];
    const float* Wo        = (const float*)d_in[7];
    const float* bo        = (const float*)d_in[8];
    const float* rel_table = (const float*)d_in[9];
    const float* ln1_g     = (const float*)d_in[10];
    const float* ln1_b     = (const float*)d_in[11];
    const float* ln2_g     = (const float*)d_in[12];
    const float* ln2_b     = (const float*)d_in[13];
    const float* W1        = (const float*)d_in[14];
    const float* b1        = (const float*)d_in[15];
    const float* W2        = (const float*)d_in[16];
    const float* b2        = (const float*)d_in[17];

    float* xbuf = (float*)d_out;

    __half *xn, *qkv, *o, *m, *wt;
    float *bqkv;
    cudaGetSymbolAddress((void**)&xn,   g_xn);
    cudaGetSymbolAddress((void**)&qkv,  g_qkv);
    cudaGetSymbolAddress((void**)&o,    g_o);
    cudaGetSymbolAddress((void**)&m,    g_m);
    cudaGetSymbolAddress((void**)&wt,   g_wt);
    cudaGetSymbolAddress((void**)&bqkv, g_bqkv);

    cudaFuncSetAttribute(mg_gemm<1>, cudaFuncAttributeMaxDynamicSharedMemorySize, MG_SMEM);
    cudaFuncSetAttribute(mg_gemm<2>, cudaFuncAttributeMaxDynamicSharedMemorySize, MG_SMEM);
    cudaFuncSetAttribute(mg_gemm<3>, cudaFuncAttributeMaxDynamicSharedMemorySize, MG_SMEM);

    cudaMemcpyAsync(xbuf, x_in, (size_t)NTOK * DIM * sizeof(float),
                    cudaMemcpyDeviceToDevice);

    // Weight transform, all layers batched via blockIdx.z
    wtrans_kernel<<<dim3(16, 16, NLAYER), 256>>>(Wq,  wt + WOFF_Q,  512, 512);
    wtrans_kernel<<<dim3(32, 16, NLAYER), 256>>>(Wkv, wt + WOFF_KV, 512, 1024);
    wtrans_kernel<<<dim3(16, 16, NLAYER), 256>>>(Wo,  wt + WOFF_O,  512, 512);
    wtrans_kernel<<<dim3(64, 16, NLAYER), 256>>>(W1,  wt + WOFF_W1, 512, 2048);
    wtrans_kernel<<<dim3(16, 64, NLAYER), 256>>>(W2,  wt + WOFF_W2, 2048, 512);
    bcat_kernel<<<dim3(NLAYER, 3), 512>>>(bq, bkv, bqkv);

    dim3 gLN(NTOK / 8), bLN(256);
    dim3 gAttn(NHEAD, 64, BATCH), bAttn(256);

    for (int l = 0; l < NLAYER; l++) {
        size_t lw = (size_t)l * WLAYER;
        const float* bov  = bo  + (size_t)l * DIM;
        const float* tab  = rel_table + (size_t)l * 225 * NHEAD;
        const float* b1v  = b1  + (size_t)l * 4 * DIM;
        const float* b2v  = b2  + (size_t)l * DIM;

        ln_kernel<<<gLN, bLN>>>(xbuf, ln1_g + (size_t)l*DIM, ln1_b + (size_t)l*DIM, xn);
        // Fused Q+KV GEMM: N=1536 over adjacent [Wq|Wkv] transposed block
        mg_gemm<3><<<dim3(12, 256), 256, MG_SMEM>>>(
            xn, wt + lw + WOFF_Q, bqkv + (size_t)l * 1536, nullptr,
            nullptr, qkv, NTOK, 1536, 512);
        attn_kernel<<<gAttn, bAttn>>>(qkv, rel_index, tab, o);
        mg_gemm<2><<<dim3(4, 256), 256, MG_SMEM>>>(
            o, wt + lw + WOFF_O, bov, xbuf, xbuf, nullptr, NTOK, 512, 512);
        ln_kernel<<<gLN, bLN>>>(xbuf, ln2_g + (size_t)l*DIM, ln2_b + (size_t)l*DIM, xn);
        mg_gemm<1><<<dim3(16, 256), 256, MG_SMEM>>>(
            xn, wt + lw + WOFF_W1, b1v, nullptr, nullptr, m, NTOK, 2048, 512);
        mg_gemm<2><<<dim3(4, 256), 256, MG_SMEM>>>(
            m, wt + lw + WOFF_W2, b2v, xbuf, xbuf, nullptr, NTOK, 512, 2048);
    }
}

// round 12
// speedup vs baseline: 1.2091x; 1.0532x over previous
#include <cuda_runtime.h>
#include <cuda_fp16.h>
#include <math.h>
#include <stdint.h>

// ---------------------------------------------------------------------------
// Swin-style transformer encoder. mma.sync fp16 GEMMs + half2 attention.
// B=8, H=W=64, D=512, NH=16, DK=32, WS=8, SH=4, L=4
// R11: GEMM BK 32 -> 64 (8 barrier regions instead of 16), SW128 swizzle.
// ---------------------------------------------------------------------------

#define BATCH 8
#define HH 64
#define WW 64
#define DIM 512
#define NHEAD 16
#define DKH 32
#define WSZ 8
#define SHF 4
#define NLAYER 4
#define NTOK (BATCH * HH * WW)          // 32768
#define SCALE 0.17677669529663687f     // 1/sqrt(32)

#define WOFF_Q  0
#define WOFF_KV 262144
#define WOFF_O  786432
#define WOFF_W1 1048576
#define WOFF_W2 2097152
#define WLAYER  3145728

// ---------------------------------------------------------------------------
// Scratch
// ---------------------------------------------------------------------------
__device__ __half g_xn  [(size_t)NTOK * DIM];
__device__ __half g_qkv [(size_t)NTOK * 1536];
__device__ __half g_o   [(size_t)NTOK * DIM];
__device__ __half g_m   [(size_t)NTOK * DIM * 4];
__device__ __half g_wt  [(size_t)NLAYER * WLAYER];
__device__ float  g_bqkv[(size_t)NLAYER * 1536];

// ---------------------------------------------------------------------------
// Helpers
// ---------------------------------------------------------------------------
__device__ __forceinline__ uint32_t smem_u32(const void* p) {
    uint32_t a;
    asm("{ .reg .u64 t; cvta.to.shared.u64 t, %1; cvt.u32.u64 %0, t; }"
        : "=r"(a) : "l"(p));
    return a;
}
__device__ __forceinline__ void cpa16(uint32_t dst, const void* src) {
    asm volatile("cp.async.cg.shared.global [%0], [%1], 16;" :: "r"(dst), "l"(src));
}
__device__ __forceinline__ void ldsm_x4(uint32_t* r, uint32_t addr) {
    asm volatile("ldmatrix.sync.aligned.m8n8.x4.shared.b16 {%0,%1,%2,%3}, [%4];"
                 : "=r"(r[0]), "=r"(r[1]), "=r"(r[2]), "=r"(r[3]) : "r"(addr));
}
__device__ __forceinline__ void mma16816(float* d, const uint32_t* a, const uint32_t* b) {
    asm volatile("mma.sync.aligned.m16n8k16.row.col.f32.f16.f16.f32 "
        "{%0,%1,%2,%3}, {%4,%5,%6,%7}, {%8,%9}, {%0,%1,%2,%3};"
        : "+f"(d[0]), "+f"(d[1]), "+f"(d[2]), "+f"(d[3])
        : "r"(a[0]), "r"(a[1]), "r"(a[2]), "r"(a[3]), "r"(b[0]), "r"(b[1]));
}
__device__ __forceinline__ float gelu_tanh(float u) {
    float t = tanhf(0.7978845608028654f * (u + 0.044715f * u * u * u));
    return 0.5f * u * (1.0f + t);
}
__device__ __forceinline__ uint32_t pack_h2(float a, float b) {
    __half2 h = __floats2half2_rn(a, b);
    return *(uint32_t*)&h;
}

// ---------------------------------------------------------------------------
// Weight transform: W[K,N] fp32 -> Wt[N,K] fp16  (blockIdx.z = layer)
// ---------------------------------------------------------------------------
__global__ void wtrans_kernel(const float* __restrict__ W,
                              __half* __restrict__ T,
                              int K, int N)
{
    W += (size_t)blockIdx.z * K * N;
    T += (size_t)blockIdx.z * WLAYER;
    __shared__ float t[32][33];
    int nb = blockIdx.x * 32, kb = blockIdx.y * 32;
    int tx = threadIdx.x & 31, ty = threadIdx.x >> 5;
#pragma unroll
    for (int i = 0; i < 32; i += 8)
        t[ty + i][tx] = W[(size_t)(kb + ty + i) * N + nb + tx];
    __syncthreads();
#pragma unroll
    for (int i = 0; i < 32; i += 8)
        T[(size_t)(nb + ty + i) * K + kb + tx] = __float2half_rn(t[tx][ty + i]);
}

// Bias concat: [bq(512) | bkv(1024)] per layer
__global__ void bcat_kernel(const float* __restrict__ bq,
                            const float* __restrict__ bkv,
                            float* __restrict__ out)
{
    int l = blockIdx.x;
    int t = blockIdx.y * 512 + threadIdx.x;
    out[(size_t)l * 1536 + t] =
        (t < 512) ? bq[(size_t)l * 512 + t] : bkv[(size_t)l * 1024 + t - 512];
}

// ---------------------------------------------------------------------------
// LayerNorm: warp per token (8 tokens / 256-thread block)
// ---------------------------------------------------------------------------
__global__ __launch_bounds__(256)
void ln_kernel(const float* __restrict__ X,
               const float* __restrict__ gam,
               const float* __restrict__ bet,
               __half* __restrict__ Y)
{
    int t  = blockIdx.x * 8 + (threadIdx.x >> 5);
    int ln = threadIdx.x & 31;
    const float4* xr = (const float4*)(X + (size_t)t * DIM);

    float4 v[4];
    float s = 0.0f, s2 = 0.0f;
#pragma unroll
    for (int j = 0; j < 4; j++) {
        v[j] = xr[ln + 32 * j];
        s  += v[j].x + v[j].y + v[j].z + v[j].w;
        s2 += fmaf(v[j].x, v[j].x, fmaf(v[j].y, v[j].y,
              fmaf(v[j].z, v[j].z, v[j].w * v[j].w)));
    }
#pragma unroll
    for (int o = 16; o > 0; o >>= 1) {
        s  += __shfl_xor_sync(0xffffffffu, s,  o);
        s2 += __shfl_xor_sync(0xffffffffu, s2, o);
    }
    float mean = s * (1.0f / DIM);
    float var  = s2 * (1.0f / DIM) - mean * mean;
    float rstd = rsqrtf(var + 1e-5f);

    uint2* yr = (uint2*)(Y + (size_t)t * DIM);
#pragma unroll
    for (int j = 0; j < 4; j++) {
        float4 g4 = ((const float4*)gam)[ln + 32 * j];
        float4 b4 = ((const float4*)bet)[ln + 32 * j];
        float o0 = (v[j].x - mean) * rstd * g4.x + b4.x;
        float o1 = (v[j].y - mean) * rstd * g4.y + b4.y;
        float o2 = (v[j].z - mean) * rstd * g4.z + b4.z;
        float o3 = (v[j].w - mean) * rstd * g4.w + b4.w;
        yr[ln + 32 * j] = make_uint2(pack_h2(o0, o1), pack_h2(o2, o3));
    }
}

// ---------------------------------------------------------------------------
// mma.sync GEMM: C[M,N] = epi(A[M,K] @ B[N,K]^T + bias)
// Tile 128x128x64, 8 warps (4x2, each 32x64), 3-stage cp.async, fp16, 2 CTA/SM.
// EPI: 1 = bias+gelu->fp16   2 = bias+res->fp32   3 = bias->fp16
// smem per stage: A 16K | B 16K = 32KB.  3 stages + 512B bias.
// Swizzle: 16B seg s of 128B row r stored at seg (s ^ (r&7)).
// ---------------------------------------------------------------------------
#define MG_STAGE 32768
#define MG_SMEM  (3 * MG_STAGE + 512)

__device__ __forceinline__ void mg_load_chunk(
    uint32_t st,
    const __half* __restrict__ A, const __half* __restrict__ B,
    int bm, int bn, int K, int k0, int tid)
{
    // A: 128 rows x 8 segs = 1024 cp (4/thread)
#pragma unroll
    for (int i = 0; i < 4; i++) {
        int ch = tid + (i << 8);
        int r  = ch >> 3;
        int s  = ch & 7;
        uint32_t off = (uint32_t)(r * 128) + (uint32_t)((s ^ (r & 7)) << 4);
        cpa16(st + off, A + (size_t)(bm + r) * K + k0 + s * 8);
    }
    // B: 128 rows x 8 segs = 1024 cp (4/thread)
#pragma unroll
    for (int i = 0; i < 4; i++) {
        int ch = tid + (i << 8);
        int r  = ch >> 3;
        int s  = ch & 7;
        uint32_t off = (uint32_t)(r * 128) + (uint32_t)((s ^ (r & 7)) << 4);
        cpa16(st + 16384 + off, B + (size_t)(bn + r) * K + k0 + s * 8);
    }
}

template<int EPI>
__global__ __launch_bounds__(256, 2)
void mg_gemm(const __half* __restrict__ A, const __half* __restrict__ B,
             const float* __restrict__ bias, const float* __restrict__ res,
             float* __restrict__ outF, __half* __restrict__ outH,
             int M, int N, int K)
{
    extern __shared__ __align__(1024) char smem[];
    const int tid  = threadIdx.x;
    const int lane = tid & 31;
    const int wid  = tid >> 5;
    const int wm   = wid & 3;
    const int wn   = wid >> 2;
    const int bm = blockIdx.y * 128, bn = blockIdx.x * 128;

    float* sbias = (float*)(smem + 3 * MG_STAGE);
    if (tid < 32)
        ((float4*)sbias)[tid] = ((const float4*)(bias + bn))[tid];

    uint32_t sb = smem_u32(smem);

    float acc[2][8][4];
#pragma unroll
    for (int mi = 0; mi < 2; mi++)
#pragma unroll
        for (int ni = 0; ni < 8; ni++)
#pragma unroll
            for (int j = 0; j < 4; j++) acc[mi][ni][j] = 0.0f;

    const int nch = K >> 6;

    mg_load_chunk(sb, A, B, bm, bn, K, 0, tid);
    asm volatile("cp.async.commit_group;");
    if (nch > 1)
        mg_load_chunk(sb + MG_STAGE, A, B, bm, bn, K, 64, tid);
    asm volatile("cp.async.commit_group;");

    const int j8 = lane & 7;
    const int a_row_off = wm * 32 + j8 + ((lane >> 3) & 1) * 8;
    const int a_seg_off = (lane >> 4);               // 0/1
    const int b_row_off = wn * 64 + j8 + ((lane >> 4) & 1) * 8;
    const int b_seg_off = ((lane >> 3) & 1);

    for (int c = 0; c < nch; c++) {
        asm volatile("cp.async.wait_group 1;");
        __syncthreads();

        if (c + 2 < nch)
            mg_load_chunk(sb + (uint32_t)((c + 2) % 3) * MG_STAGE,
                          A, B, bm, bn, K, (c + 2) << 6, tid);
        asm volatile("cp.async.commit_group;");

        uint32_t st = sb + (uint32_t)(c % 3) * MG_STAGE;

#pragma unroll
        for (int kk = 0; kk < 4; kk++) {
            uint32_t a_f[2][4];
#pragma unroll
            for (int mi = 0; mi < 2; mi++) {
                int row = a_row_off + mi * 16;
                int seg = kk * 2 + a_seg_off;
                uint32_t off = (uint32_t)(row * 128) +
                               (uint32_t)((seg ^ (row & 7)) << 4);
                ldsm_x4(a_f[mi], st + off);
            }
            uint32_t b_f[4][4];
#pragma unroll
            for (int pi = 0; pi < 4; pi++) {
                int row = b_row_off + pi * 16;
                int seg = kk * 2 + b_seg_off;
                uint32_t off = (uint32_t)(row * 128) +
                               (uint32_t)((seg ^ (row & 7)) << 4);
                ldsm_x4(b_f[pi], st + 16384 + off);
            }
#pragma unroll
            for (int mi = 0; mi < 2; mi++)
#pragma unroll
                for (int ni = 0; ni < 8; ni++)
                    mma16816(acc[mi][ni], a_f[mi], &b_f[ni >> 1][(ni & 1) * 2]);
        }
    }
    __syncthreads();

#pragma unroll
    for (int mi = 0; mi < 2; mi++) {
        int r0 = bm + wm * 32 + mi * 16 + (lane >> 2);
#pragma unroll
        for (int ni = 0; ni < 8; ni++) {
            int cb = wn * 64 + ni * 8 + 2 * (lane & 3);
            float bv0 = sbias[cb], bv1 = sbias[cb + 1];
            float v0 = acc[mi][ni][0] + bv0;
            float v1 = acc[mi][ni][1] + bv1;
            float v2 = acc[mi][ni][2] + bv0;
            float v3 = acc[mi][ni][3] + bv1;
            size_t g0 = (size_t)r0 * N + bn + cb;
            size_t g1 = (size_t)(r0 + 8) * N + bn + cb;
            if (EPI == 2) {
                float2 q0 = *(const float2*)(res + g0);
                float2 q1 = *(const float2*)(res + g1);
                *(float2*)(outF + g0) = make_float2(v0 + q0.x, v1 + q0.y);
                *(float2*)(outF + g1) = make_float2(v2 + q1.x, v3 + q1.y);
            } else if (EPI == 3) {
                *(uint32_t*)(outH + g0) = pack_h2(v0, v1);
                *(uint32_t*)(outH + g1) = pack_h2(v2, v3);
            } else {
                v0 = gelu_tanh(v0); v1 = gelu_tanh(v1);
                v2 = gelu_tanh(v2); v3 = gelu_tanh(v3);
                *(uint32_t*)(outH + g0) = pack_h2(v0, v1);
                *(uint32_t*)(outH + g1) = pack_h2(v2, v3);
            }
        }
    }
}

// ---------------------------------------------------------------------------
// Windowed attention. Reads packed QKV [NTOK,1536] (q|k|v), writes fp16 O.
// ---------------------------------------------------------------------------
__global__ __launch_bounds__(256)
void attn_kernel(const __half* __restrict__ QKV,
                 const int*   __restrict__ relIdx,
                 const float* __restrict__ table,
                 __half* __restrict__ O)
{
    __shared__ __half2 sQ[64][20];
    __shared__ __half2 sK[64][20];
    __shared__ __half2 sV[64][20];
    __shared__ float   sA[64][65];
    __shared__ int     sTok[64];
    __shared__ int     sLab[64];
    __shared__ float   sTab[225];

    int h   = blockIdx.x;
    int win = blockIdx.y;
    int b   = blockIdx.z;
    int nwh = win >> 3, nww = win & 7;
    int tid = threadIdx.x;

    if (tid < 64) {
        int i = tid >> 3, j = tid & 7;
        int gh = (nwh * WSZ + i + SHF) & (HH - 1);
        int gw = (nww * WSZ + j + SHF) & (WW - 1);
        sTok[tid] = ((b * HH + gh) << 6) + gw;
        int ih = nwh * WSZ + i, iw = nww * WSZ + j;
        int rh = (ih >= HH - WSZ) + (ih >= HH - SHF);
        int rw = (iw >= WW - WSZ) + (iw >= WW - SHF);
        sLab[tid] = rh * 3 + rw;
    }
    if (tid < 225) sTab[tid] = table[tid * NHEAD + h];
    __syncthreads();

    {
        int r  = tid >> 2;
        int sg = tid & 3;
        size_t base = (size_t)sTok[r] * 1536 + h * DKH + sg * 8;
        *(uint4*)&sQ[r][sg * 4] = *(const uint4*)(QKV + base);
        *(uint4*)&sK[r][sg * 4] = *(const uint4*)(QKV + base + 512);
        *(uint4*)&sV[r][sg * 4] = *(const uint4*)(QKV + base + 1024);
    }
    __syncthreads();

    const int r0 = tid >> 3;
    const int cl = tid & 7;

    {
        float2 q0[16], q1[16];
#pragma unroll
        for (int d = 0; d < 16; d++) {
            q0[d] = __half22float2(sQ[r0][d]);
            q1[d] = __half22float2(sQ[r0 + 32][d]);
        }
        int lab0 = sLab[r0], lab1 = sLab[r0 + 32];
        float sc0[8], sc1[8];
#pragma unroll
        for (int c = 0; c < 8; c++) {
            int col = cl + (c << 3);
            float a0 = 0.0f, a1 = 0.0f;
#pragma unroll
            for (int d = 0; d < 16; d++) {
                float2 k2 = __half22float2(sK[col][d]);
                a0 = fmaf(q0[d].x, k2.x, a0);
                a0 = fmaf(q0[d].y, k2.y, a0);
                a1 = fmaf(q1[d].x, k2.x, a1);
                a1 = fmaf(q1[d].y, k2.y, a1);
            }
            int lc = sLab[col];
            float bi0 = sTab[relIdx[r0 * 64 + col]];
            float bi1 = sTab[relIdx[(r0 + 32) * 64 + col]];
            a0 = a0 * SCALE + bi0;
            a1 = a1 * SCALE + bi1;
            if (lab0 != lc) a0 = -1e9f;
            if (lab1 != lc) a1 = -1e9f;
            sc0[c] = a0; sc1[c] = a1;
        }
        float m0 = sc0[0], m1 = sc1[0];
#pragma unroll
        for (int c = 1; c < 8; c++) { m0 = fmaxf(m0, sc0[c]); m1 = fmaxf(m1, sc1[c]); }
#pragma unroll
        for (int o = 1; o < 8; o <<= 1) {
            m0 = fmaxf(m0, __shfl_xor_sync(0xffffffffu, m0, o));
            m1 = fmaxf(m1, __shfl_xor_sync(0xffffffffu, m1, o));
        }
        float s0 = 0.0f, s1 = 0.0f;
#pragma unroll
        for (int c = 0; c < 8; c++) {
            sc0[c] = __expf(sc0[c] - m0); s0 += sc0[c];
            sc1[c] = __expf(sc1[c] - m1); s1 += sc1[c];
        }
#pragma unroll
        for (int o = 1; o < 8; o <<= 1) {
            s0 += __shfl_xor_sync(0xffffffffu, s0, o);
            s1 += __shfl_xor_sync(0xffffffffu, s1, o);
        }
        float i0 = 1.0f / s0, i1 = 1.0f / s1;
#pragma unroll
        for (int c = 0; c < 8; c++) {
            int col = cl + (c << 3);
            sA[r0][col]      = sc0[c] * i0;
            sA[r0 + 32][col] = sc1[c] * i1;
        }
    }
    __syncthreads();

    {
        const int dh = (tid & 7) * 2;
        float o00 = 0, o01 = 0, o02 = 0, o03 = 0;
        float o10 = 0, o11 = 0, o12 = 0, o13 = 0;
#pragma unroll
        for (int k = 0; k < 64; k++) {
            float a0 = sA[r0][k];
            float a1 = sA[r0 + 32][k];
            uint2 vv = *(uint2*)&sV[k][dh];
            float2 v0 = __half22float2(*(__half2*)&vv.x);
            float2 v1 = __half22float2(*(__half2*)&vv.y);
            o00 = fmaf(a0, v0.x, o00); o01 = fmaf(a0, v0.y, o01);
            o02 = fmaf(a0, v1.x, o02); o03 = fmaf(a0, v1.y, o03);
            o10 = fmaf(a1, v0.x, o10); o11 = fmaf(a1, v0.y, o11);
            o12 = fmaf(a1, v1.x, o12); o13 = fmaf(a1, v1.y, o13);
        }
        size_t b0 = (size_t)sTok[r0] * DIM + h * DKH + dh * 2;
        *(uint2*)(O + b0) = make_uint2(pack_h2(o00, o01), pack_h2(o02, o03));
        size_t b1 = (size_t)sTok[r0 + 32] * DIM + h * DKH + dh * 2;
        *(uint2*)(O + b1) = make_uint2(pack_h2(o10, o11), pack_h2(o12, o13));
    }
}

// ---------------------------------------------------------------------------
// Launch
// ---------------------------------------------------------------------------
extern "C" void kernel_launch(void* const* d_in, const int* in_sizes, int n_in,
                              void* d_out, int out_size)
{
    const float* x_in      = (const float*)d_in[0];
    const int*   rel_index = (const int*)  d_in[2];
    const float* Wq        = (const float*)d_in[3];
    const float* bq        = (const float*)d_in[4];
    const float* Wkv       = (const float*)d_in[5];
    const float* bkv       = (const float*)d_in[6];
    const float* Wo        = (const float*)d_in[7];
    const float* bo        = (const float*)d_in[8];
    const float* rel_table = (const float*)d_in[9];
    const float* ln1_g     = (const float*)d_in[10];
    const float* ln1_b     = (const float*)d_in[11];
    const float* ln2_g     = (const float*)d_in[12];
    const float* ln2_b     = (const float*)d_in[13];
    const float* W1        = (const float*)d_in[14];
    const float* b1        = (const float*)d_in[15];
    const float* W2        = (const float*)d_in[16];
    const float* b2        = (const float*)d_in[17];

    float* xbuf = (float*)d_out;

    __half *xn, *qkv, *o, *m, *wt;
    float *bqkv;
    cudaGetSymbolAddress((void**)&xn,   g_xn);
    cudaGetSymbolAddress((void**)&qkv,  g_qkv);
    cudaGetSymbolAddress((void**)&o,    g_o);
    cudaGetSymbolAddress((void**)&m,    g_m);
    cudaGetSymbolAddress((void**)&wt,   g_wt);
    cudaGetSymbolAddress((void**)&bqkv, g_bqkv);

    cudaFuncSetAttribute(mg_gemm<1>, cudaFuncAttributeMaxDynamicSharedMemorySize, MG_SMEM);
    cudaFuncSetAttribute(mg_gemm<2>, cudaFuncAttributeMaxDynamicSharedMemorySize, MG_SMEM);
    cudaFuncSetAttribute(mg_gemm<3>, cudaFuncAttributeMaxDynamicSharedMemorySize, MG_SMEM);

    cudaMemcpyAsync(xbuf, x_in, (size_t)NTOK * DIM * sizeof(float),
                    cudaMemcpyDeviceToDevice);

    // Weight transform, all layers batched via blockIdx.z
    wtrans_kernel<<<dim3(16, 16, NLAYER), 256>>>(Wq,  wt + WOFF_Q,  512, 512);
    wtrans_kernel<<<dim3(32, 16, NLAYER), 256>>>(Wkv, wt + WOFF_KV, 512, 1024);
    wtrans_kernel<<<dim3(16, 16, NLAYER), 256>>>(Wo,  wt + WOFF_O,  512, 512);
    wtrans_kernel<<<dim3(64, 16, NLAYER), 256>>>(W1,  wt + WOFF_W1, 512, 2048);
    wtrans_kernel<<<dim3(16, 64, NLAYER), 256>>>(W2,  wt + WOFF_W2, 2048, 512);
    bcat_kernel<<<dim3(NLAYER, 3), 512>>>(bq, bkv, bqkv);

    dim3 gLN(NTOK / 8), bLN(256);
    dim3 gAttn(NHEAD, 64, BATCH), bAttn(256);

    for (int l = 0; l < NLAYER; l++) {
        size_t lw = (size_t)l * WLAYER;
        const float* bov  = bo  + (size_t)l * DIM;
        const float* tab  = rel_table + (size_t)l * 225 * NHEAD;
        const float* b1v  = b1  + (size_t)l * 4 * DIM;
        const float* b2v  = b2  + (size_t)l * DIM;

        ln_kernel<<<gLN, bLN>>>(xbuf, ln1_g + (size_t)l*DIM, ln1_b + (size_t)l*DIM, xn);
        // Fused Q+KV GEMM: N=1536 over adjacent [Wq|Wkv] transposed block
        mg_gemm<3><<<dim3(12, 256), 256, MG_SMEM>>>(
            xn, wt + lw + WOFF_Q, bqkv + (size_t)l * 1536, nullptr,
            nullptr, qkv, NTOK, 1536, 512);
        attn_kernel<<<gAttn, bAttn>>>(qkv, rel_index, tab, o);
        mg_gemm<2><<<dim3(4, 256), 256, MG_SMEM>>>(
            o, wt + lw + WOFF_O, bov, xbuf, xbuf, nullptr, NTOK, 512, 512);
        ln_kernel<<<gLN, bLN>>>(xbuf, ln2_g + (size_t)l*DIM, ln2_b + (size_t)l*DIM, xn);
        mg_gemm<1><<<dim3(16, 256), 256, MG_SMEM>>>(
            xn, wt + lw + WOFF_W1, b1v, nullptr, nullptr, m, NTOK, 2048, 512);
        mg_gemm<2><<<dim3(4, 256), 256, MG_SMEM>>>(
            m, wt + lw + WOFF_W2, b2v, xbuf, xbuf, nullptr, NTOK, 512, 2048);
    }
}

// round 16
// speedup vs baseline: 1.3345x; 1.1038x over previous
#include <cuda_runtime.h>
#include <cuda_fp16.h>
#include <math.h>
#include <stdint.h>

// ---------------------------------------------------------------------------
// Swin-style transformer encoder. mma.sync fp16 GEMMs + mma attention.
// B=8, H=W=64, D=512, NH=16, DK=32, WS=8, SH=4, L=4
// R16 = R13 resubmitted verbatim (R14/R15 were infra failures, no signal).
// ---------------------------------------------------------------------------

#define BATCH 8
#define HH 64
#define WW 64
#define DIM 512
#define NHEAD 16
#define DKH 32
#define WSZ 8
#define SHF 4
#define NLAYER 4
#define NTOK (BATCH * HH * WW)          // 32768
#define SCALE 0.17677669529663687f     // 1/sqrt(32)

#define WOFF_Q  0
#define WOFF_KV 262144
#define WOFF_O  786432
#define WOFF_W1 1048576
#define WOFF_W2 2097152
#define WLAYER  3145728

// ---------------------------------------------------------------------------
// Scratch
// ---------------------------------------------------------------------------
__device__ __half g_xn  [(size_t)NTOK * DIM];
__device__ __half g_qkv [(size_t)NTOK * 1536];
__device__ __half g_o   [(size_t)NTOK * DIM];
__device__ __half g_m   [(size_t)NTOK * DIM * 4];
__device__ __half g_wt  [(size_t)NLAYER * WLAYER];
__device__ float  g_bqkv[(size_t)NLAYER * 1536];

// ---------------------------------------------------------------------------
// Helpers
// ---------------------------------------------------------------------------
__device__ __forceinline__ uint32_t smem_u32(const void* p) {
    uint32_t a;
    asm("{ .reg .u64 t; cvta.to.shared.u64 t, %1; cvt.u32.u64 %0, t; }"
        : "=r"(a) : "l"(p));
    return a;
}
__device__ __forceinline__ void cpa16(uint32_t dst, const void* src) {
    asm volatile("cp.async.cg.shared.global [%0], [%1], 16;" :: "r"(dst), "l"(src));
}
__device__ __forceinline__ void ldsm_x4(uint32_t* r, uint32_t addr) {
    asm volatile("ldmatrix.sync.aligned.m8n8.x4.shared.b16 {%0,%1,%2,%3}, [%4];"
                 : "=r"(r[0]), "=r"(r[1]), "=r"(r[2]), "=r"(r[3]) : "r"(addr));
}
__device__ __forceinline__ void ldsm_x4_t(uint32_t* r, uint32_t addr) {
    asm volatile("ldmatrix.sync.aligned.m8n8.x4.trans.shared.b16 {%0,%1,%2,%3}, [%4];"
                 : "=r"(r[0]), "=r"(r[1]), "=r"(r[2]), "=r"(r[3]) : "r"(addr));
}
__device__ __forceinline__ void mma16816(float* d, const uint32_t* a, const uint32_t* b) {
    asm volatile("mma.sync.aligned.m16n8k16.row.col.f32.f16.f16.f32 "
        "{%0,%1,%2,%3}, {%4,%5,%6,%7}, {%8,%9}, {%0,%1,%2,%3};"
        : "+f"(d[0]), "+f"(d[1]), "+f"(d[2]), "+f"(d[3])
        : "r"(a[0]), "r"(a[1]), "r"(a[2]), "r"(a[3]), "r"(b[0]), "r"(b[1]));
}
__device__ __forceinline__ float gelu_tanh(float u) {
    float t = tanhf(0.7978845608028654f * (u + 0.044715f * u * u * u));
    return 0.5f * u * (1.0f + t);
}
__device__ __forceinline__ uint32_t pack_h2(float a, float b) {
    __half2 h = __floats2half2_rn(a, b);
    return *(uint32_t*)&h;
}

// ---------------------------------------------------------------------------
// Weight transform: W[K,N] fp32 -> Wt[N,K] fp16  (blockIdx.z = layer)
// ---------------------------------------------------------------------------
__global__ void wtrans_kernel(const float* __restrict__ W,
                              __half* __restrict__ T,
                              int K, int N)
{
    W += (size_t)blockIdx.z * K * N;
    T += (size_t)blockIdx.z * WLAYER;
    __shared__ float t[32][33];
    int nb = blockIdx.x * 32, kb = blockIdx.y * 32;
    int tx = threadIdx.x & 31, ty = threadIdx.x >> 5;
#pragma unroll
    for (int i = 0; i < 32; i += 8)
        t[ty + i][tx] = W[(size_t)(kb + ty + i) * N + nb + tx];
    __syncthreads();
#pragma unroll
    for (int i = 0; i < 32; i += 8)
        T[(size_t)(nb + ty + i) * K + kb + tx] = __float2half_rn(t[tx][ty + i]);
}

// Bias concat: [bq(512) | bkv(1024)] per layer
__global__ void bcat_kernel(const float* __restrict__ bq,
                            const float* __restrict__ bkv,
                            float* __restrict__ out)
{
    int l = blockIdx.x;
    int t = blockIdx.y * 512 + threadIdx.x;
    out[(size_t)l * 1536 + t] =
        (t < 512) ? bq[(size_t)l * 512 + t] : bkv[(size_t)l * 1024 + t - 512];
}

// ---------------------------------------------------------------------------
// LayerNorm: warp per token (8 tokens / 256-thread block)
// ---------------------------------------------------------------------------
__global__ __launch_bounds__(256)
void ln_kernel(const float* __restrict__ X,
               const float* __restrict__ gam,
               const float* __restrict__ bet,
               __half* __restrict__ Y)
{
    int t  = blockIdx.x * 8 + (threadIdx.x >> 5);
    int ln = threadIdx.x & 31;
    const float4* xr = (const float4*)(X + (size_t)t * DIM);

    float4 v[4];
    float s = 0.0f, s2 = 0.0f;
#pragma unroll
    for (int j = 0; j < 4; j++) {
        v[j] = xr[ln + 32 * j];
        s  += v[j].x + v[j].y + v[j].z + v[j].w;
        s2 += fmaf(v[j].x, v[j].x, fmaf(v[j].y, v[j].y,
              fmaf(v[j].z, v[j].z, v[j].w * v[j].w)));
    }
#pragma unroll
    for (int o = 16; o > 0; o >>= 1) {
        s  += __shfl_xor_sync(0xffffffffu, s,  o);
        s2 += __shfl_xor_sync(0xffffffffu, s2, o);
    }
    float mean = s * (1.0f / DIM);
    float var  = s2 * (1.0f / DIM) - mean * mean;
    float rstd = rsqrtf(var + 1e-5f);

    uint2* yr = (uint2*)(Y + (size_t)t * DIM);
#pragma unroll
    for (int j = 0; j < 4; j++) {
        float4 g4 = ((const float4*)gam)[ln + 32 * j];
        float4 b4 = ((const float4*)bet)[ln + 32 * j];
        float o0 = (v[j].x - mean) * rstd * g4.x + b4.x;
        float o1 = (v[j].y - mean) * rstd * g4.y + b4.y;
        float o2 = (v[j].z - mean) * rstd * g4.z + b4.z;
        float o3 = (v[j].w - mean) * rstd * g4.w + b4.w;
        yr[ln + 32 * j] = make_uint2(pack_h2(o0, o1), pack_h2(o2, o3));
    }
}

// ---------------------------------------------------------------------------
// mma.sync GEMM: C[M,N] = epi(A[M,K] @ B[N,K]^T + bias)
// Tile 128x128x64, 8 warps (4x2, each 32x64), 3-stage cp.async, fp16, 2 CTA/SM.
// EPI: 1 = bias+gelu->fp16   2 = bias+res->fp32   3 = bias->fp16
// ---------------------------------------------------------------------------
#define MG_STAGE 32768
#define MG_SMEM  (3 * MG_STAGE + 512)

__device__ __forceinline__ void mg_load_chunk(
    uint32_t st,
    const __half* __restrict__ A, const __half* __restrict__ B,
    int bm, int bn, int K, int k0, int tid)
{
#pragma unroll
    for (int i = 0; i < 4; i++) {
        int ch = tid + (i << 8);
        int r  = ch >> 3;
        int s  = ch & 7;
        uint32_t off = (uint32_t)(r * 128) + (uint32_t)((s ^ (r & 7)) << 4);
        cpa16(st + off, A + (size_t)(bm + r) * K + k0 + s * 8);
    }
#pragma unroll
    for (int i = 0; i < 4; i++) {
        int ch = tid + (i << 8);
        int r  = ch >> 3;
        int s  = ch & 7;
        uint32_t off = (uint32_t)(r * 128) + (uint32_t)((s ^ (r & 7)) << 4);
        cpa16(st + 16384 + off, B + (size_t)(bn + r) * K + k0 + s * 8);
    }
}

template<int EPI>
__global__ __launch_bounds__(256, 2)
void mg_gemm(const __half* __restrict__ A, const __half* __restrict__ B,
             const float* __restrict__ bias, const float* __restrict__ res,
             float* __restrict__ outF, __half* __restrict__ outH,
             int M, int N, int K)
{
    extern __shared__ __align__(1024) char smem[];
    const int tid  = threadIdx.x;
    const int lane = tid & 31;
    const int wid  = tid >> 5;
    const int wm   = wid & 3;
    const int wn   = wid >> 2;
    const int bm = blockIdx.y * 128, bn = blockIdx.x * 128;

    float* sbias = (float*)(smem + 3 * MG_STAGE);
    if (tid < 32)
        ((float4*)sbias)[tid] = ((const float4*)(bias + bn))[tid];

    uint32_t sb = smem_u32(smem);

    float acc[2][8][4];
#pragma unroll
    for (int mi = 0; mi < 2; mi++)
#pragma unroll
        for (int ni = 0; ni < 8; ni++)
#pragma unroll
            for (int j = 0; j < 4; j++) acc[mi][ni][j] = 0.0f;

    const int nch = K >> 6;

    mg_load_chunk(sb, A, B, bm, bn, K, 0, tid);
    asm volatile("cp.async.commit_group;");
    if (nch > 1)
        mg_load_chunk(sb + MG_STAGE, A, B, bm, bn, K, 64, tid);
    asm volatile("cp.async.commit_group;");

    const int j8 = lane & 7;
    const int a_row_off = wm * 32 + j8 + ((lane >> 3) & 1) * 8;
    const int a_seg_off = (lane >> 4);               // 0/1
    const int b_row_off = wn * 64 + j8 + ((lane >> 4) & 1) * 8;
    const int b_seg_off = ((lane >> 3) & 1);

    for (int c = 0; c < nch; c++) {
        asm volatile("cp.async.wait_group 1;");
        __syncthreads();

        if (c + 2 < nch)
            mg_load_chunk(sb + (uint32_t)((c + 2) % 3) * MG_STAGE,
                          A, B, bm, bn, K, (c + 2) << 6, tid);
        asm volatile("cp.async.commit_group;");

        uint32_t st = sb + (uint32_t)(c % 3) * MG_STAGE;

#pragma unroll
        for (int kk = 0; kk < 4; kk++) {
            uint32_t a_f[2][4];
#pragma unroll
            for (int mi = 0; mi < 2; mi++) {
                int row = a_row_off + mi * 16;
                int seg = kk * 2 + a_seg_off;
                uint32_t off = (uint32_t)(row * 128) +
                               (uint32_t)((seg ^ (row & 7)) << 4);
                ldsm_x4(a_f[mi], st + off);
            }
            uint32_t b_f[4][4];
#pragma unroll
            for (int pi = 0; pi < 4; pi++) {
                int row = b_row_off + pi * 16;
                int seg = kk * 2 + b_seg_off;
                uint32_t off = (uint32_t)(row * 128) +
                               (uint32_t)((seg ^ (row & 7)) << 4);
                ldsm_x4(b_f[pi], st + 16384 + off);
            }
#pragma unroll
            for (int mi = 0; mi < 2; mi++)
#pragma unroll
                for (int ni = 0; ni < 8; ni++)
                    mma16816(acc[mi][ni], a_f[mi], &b_f[ni >> 1][(ni & 1) * 2]);
        }
    }
    __syncthreads();

#pragma unroll
    for (int mi = 0; mi < 2; mi++) {
        int r0 = bm + wm * 32 + mi * 16 + (lane >> 2);
#pragma unroll
        for (int ni = 0; ni < 8; ni++) {
            int cb = wn * 64 + ni * 8 + 2 * (lane & 3);
            float bv0 = sbias[cb], bv1 = sbias[cb + 1];
            float v0 = acc[mi][ni][0] + bv0;
            float v1 = acc[mi][ni][1] + bv1;
            float v2 = acc[mi][ni][2] + bv0;
            float v3 = acc[mi][ni][3] + bv1;
            size_t g0 = (size_t)r0 * N + bn + cb;
            size_t g1 = (size_t)(r0 + 8) * N + bn + cb;
            if (EPI == 2) {
                float2 q0 = *(const float2*)(res + g0);
                float2 q1 = *(const float2*)(res + g1);
                *(float2*)(outF + g0) = make_float2(v0 + q0.x, v1 + q0.y);
                *(float2*)(outF + g1) = make_float2(v2 + q1.x, v3 + q1.y);
            } else if (EPI == 3) {
                *(uint32_t*)(outH + g0) = pack_h2(v0, v1);
                *(uint32_t*)(outH + g1) = pack_h2(v2, v3);
            } else {
                v0 = gelu_tanh(v0); v1 = gelu_tanh(v1);
                v2 = gelu_tanh(v2); v3 = gelu_tanh(v3);
                *(uint32_t*)(outH + g0) = pack_h2(v0, v1);
                *(uint32_t*)(outH + g1) = pack_h2(v2, v3);
            }
        }
    }
}

// ---------------------------------------------------------------------------
// Windowed attention on tensor cores.
// QK^T: Q[64,32] @ K[64,32]^T via mma (A=Q, B=K, both row-major).
// softmax in fp32 via smem staging; AV: P[64,64] @ V[64,32] with B=V via
// ldmatrix.trans. Warp grid 4x2 (wm rows 16, wn half of cols/dims).
// Row pads: Q/K/V 40 halves, P 72 halves, S 68 floats (conflict-free ldsm).
// ---------------------------------------------------------------------------
__global__ __launch_bounds__(256)
void attn_kernel(const __half* __restrict__ QKV,
                 const int*   __restrict__ relIdx,
                 const float* __restrict__ table,
                 __half* __restrict__ O)
{
    __shared__ __half sQ[64][40];
    __shared__ __half sK[64][40];
    __shared__ __half sV[64][40];
    __shared__ float  sS[64][68];
    __shared__ __half sP[64][72];
    __shared__ int    sTok[64];
    __shared__ int    sLab[64];
    __shared__ float  sTab[225];

    int h   = blockIdx.x;
    int win = blockIdx.y;
    int b   = blockIdx.z;
    int nwh = win >> 3, nww = win & 7;
    int tid = threadIdx.x;
    const int lane = tid & 31;
    const int wid  = tid >> 5;
    const int wm   = wid & 3;
    const int wn   = wid >> 2;

    if (tid < 64) {
        int i = tid >> 3, j = tid & 7;
        int gh = (nwh * WSZ + i + SHF) & (HH - 1);
        int gw = (nww * WSZ + j + SHF) & (WW - 1);
        sTok[tid] = ((b * HH + gh) << 6) + gw;
        int ih = nwh * WSZ + i, iw = nww * WSZ + j;
        int rh = (ih >= HH - WSZ) + (ih >= HH - SHF);
        int rw = (iw >= WW - WSZ) + (iw >= WW - SHF);
        sLab[tid] = rh * 3 + rw;
    }
    if (tid < 225) sTab[tid] = table[tid * NHEAD + h];
    __syncthreads();

    {
        int r  = tid >> 2;
        int sg = tid & 3;
        size_t base = (size_t)sTok[r] * 1536 + h * DKH + sg * 8;
        *(uint4*)&sQ[r][sg * 8] = *(const uint4*)(QKV + base);
        *(uint4*)&sK[r][sg * 8] = *(const uint4*)(QKV + base + 512);
        *(uint4*)&sV[r][sg * 8] = *(const uint4*)(QKV + base + 1024);
    }
    __syncthreads();

    // ---- QK^T on tensor cores ----
    const int j8 = lane & 7;
    const int a_row = wm * 16 + j8 + ((lane >> 3) & 1) * 8;   // (lane&15)
    const int a_colh = (lane >> 4) << 3;
    const int b_rowo = wn * 32 + j8 + ((lane >> 4) & 1) * 8;
    const int b_colh = ((lane >> 3) & 1) << 3;

    {
        float accS[4][4];
#pragma unroll
        for (int ni = 0; ni < 4; ni++)
#pragma unroll
            for (int j = 0; j < 4; j++) accS[ni][j] = 0.0f;

#pragma unroll
        for (int kk = 0; kk < 2; kk++) {
            uint32_t af[4];
            ldsm_x4(af, smem_u32(&sQ[a_row][kk * 16 + a_colh]));
            uint32_t bf[2][4];
#pragma unroll
            for (int pi = 0; pi < 2; pi++)
                ldsm_x4(bf[pi], smem_u32(&sK[b_rowo + pi * 16][kk * 16 + b_colh]));
#pragma unroll
            for (int ni = 0; ni < 4; ni++)
                mma16816(accS[ni], af, &bf[ni >> 1][(ni & 1) * 2]);
        }

        // scale + rel-pos bias + shift mask -> sS
        int m0 = wm * 16 + (lane >> 2);
        int m1 = m0 + 8;
        int lab0 = sLab[m0], lab1 = sLab[m1];
#pragma unroll
        for (int ni = 0; ni < 4; ni++) {
            int c0 = wn * 32 + ni * 8 + 2 * (lane & 3);
            int lc0 = sLab[c0], lc1 = sLab[c0 + 1];
            float v00 = accS[ni][0] * SCALE + sTab[relIdx[m0 * 64 + c0]];
            float v01 = accS[ni][1] * SCALE + sTab[relIdx[m0 * 64 + c0 + 1]];
            float v10 = accS[ni][2] * SCALE + sTab[relIdx[m1 * 64 + c0]];
            float v11 = accS[ni][3] * SCALE + sTab[relIdx[m1 * 64 + c0 + 1]];
            if (lab0 != lc0) v00 = -1e9f;
            if (lab0 != lc1) v01 = -1e9f;
            if (lab1 != lc0) v10 = -1e9f;
            if (lab1 != lc1) v11 = -1e9f;
            *(float2*)&sS[m0][c0] = make_float2(v00, v01);
            *(float2*)&sS[m1][c0] = make_float2(v10, v11);
        }
    }
    __syncthreads();

    // ---- softmax (4 threads per row, 16 contiguous cols each) ----
    {
        int rr = tid >> 2;
        int qd = tid & 3;
        float4 v0 = *(float4*)&sS[rr][qd * 16 + 0];
        float4 v1 = *(float4*)&sS[rr][qd * 16 + 4];
        float4 v2 = *(float4*)&sS[rr][qd * 16 + 8];
        float4 v3 = *(float4*)&sS[rr][qd * 16 + 12];
        float mx = fmaxf(fmaxf(fmaxf(v0.x, v0.y), fmaxf(v0.z, v0.w)),
                         fmaxf(fmaxf(v1.x, v1.y), fmaxf(v1.z, v1.w)));
        mx = fmaxf(mx, fmaxf(fmaxf(fmaxf(v2.x, v2.y), fmaxf(v2.z, v2.w)),
                             fmaxf(fmaxf(v3.x, v3.y), fmaxf(v3.z, v3.w))));
        mx = fmaxf(mx, __shfl_xor_sync(0xffffffffu, mx, 1));
        mx = fmaxf(mx, __shfl_xor_sync(0xffffffffu, mx, 2));
        float e[16];
        e[0]=__expf(v0.x-mx); e[1]=__expf(v0.y-mx); e[2]=__expf(v0.z-mx); e[3]=__expf(v0.w-mx);
        e[4]=__expf(v1.x-mx); e[5]=__expf(v1.y-mx); e[6]=__expf(v1.z-mx); e[7]=__expf(v1.w-mx);
        e[8]=__expf(v2.x-mx); e[9]=__expf(v2.y-mx); e[10]=__expf(v2.z-mx); e[11]=__expf(v2.w-mx);
        e[12]=__expf(v3.x-mx); e[13]=__expf(v3.y-mx); e[14]=__expf(v3.z-mx); e[15]=__expf(v3.w-mx);
        float sum = 0.0f;
#pragma unroll
        for (int i = 0; i < 16; i++) sum += e[i];
        sum += __shfl_xor_sync(0xffffffffu, sum, 1);
        sum += __shfl_xor_sync(0xffffffffu, sum, 2);
        float inv = 1.0f / sum;
        uint4 p0, p1;
        p0.x = pack_h2(e[0]*inv,  e[1]*inv);  p0.y = pack_h2(e[2]*inv,  e[3]*inv);
        p0.z = pack_h2(e[4]*inv,  e[5]*inv);  p0.w = pack_h2(e[6]*inv,  e[7]*inv);
        p1.x = pack_h2(e[8]*inv,  e[9]*inv);  p1.y = pack_h2(e[10]*inv, e[11]*inv);
        p1.z = pack_h2(e[12]*inv, e[13]*inv); p1.w = pack_h2(e[14]*inv, e[15]*inv);
        *(uint4*)&sP[rr][qd * 16 + 0] = p0;
        *(uint4*)&sP[rr][qd * 16 + 8] = p1;
    }
    __syncthreads();

    // ---- AV on tensor cores: P[64,64] @ V[64,32], B = V via ldsm.trans ----
    {
        float accO[2][4];
#pragma unroll
        for (int ni = 0; ni < 2; ni++)
#pragma unroll
            for (int j = 0; j < 4; j++) accO[ni][j] = 0.0f;

#pragma unroll
        for (int kk = 0; kk < 4; kk++) {
            uint32_t af[4];
            ldsm_x4(af, smem_u32(&sP[a_row][kk * 16 + a_colh]));
            uint32_t bf[4];
            ldsm_x4_t(bf, smem_u32(&sV[kk * 16 + (lane & 15)][wn * 16 + ((lane >> 4) << 3)]));
            mma16816(accO[0], af, &bf[0]);
            mma16816(accO[1], af, &bf[2]);
        }

        int m0 = wm * 16 + (lane >> 2);
        int m1 = m0 + 8;
        size_t g0 = (size_t)sTok[m0] * DIM + h * DKH;
        size_t g1 = (size_t)sTok[m1] * DIM + h * DKH;
#pragma unroll
        for (int ni = 0; ni < 2; ni++) {
            int c = wn * 16 + ni * 8 + 2 * (lane & 3);
            *(uint32_t*)(O + g0 + c) = pack_h2(accO[ni][0], accO[ni][1]);
            *(uint32_t*)(O + g1 + c) = pack_h2(accO[ni][2], accO[ni][3]);
        }
    }
}

// ---------------------------------------------------------------------------
// Launch
// ---------------------------------------------------------------------------
extern "C" void kernel_launch(void* const* d_in, const int* in_sizes, int n_in,
                              void* d_out, int out_size)
{
    const float* x_in      = (const float*)d_in[0];
    const int*   rel_index = (const int*)  d_in[2];
    const float* Wq        = (const float*)d_in[3];
    const float* bq        = (const float*)d_in[4];
    const float* Wkv       = (const float*)d_in[5];
    const float* bkv       = (const float*)d_in[6];
    const float* Wo        = (const float*)d_in[7];
    const float* bo        = (const float*)d_in[8];
    const float* rel_table = (const float*)d_in[9];
    const float* ln1_g     = (const float*)d_in[10];
    const float* ln1_b     = (const float*)d_in[11];
    const float* ln2_g     = (const float*)d_in[12];
    const float* ln2_b     = (const float*)d_in[13];
    const float* W1        = (const float*)d_in[14];
    const float* b1        = (const float*)d_in[15];
    const float* W2        = (const float*)d_in[16];
    const float* b2        = (const float*)d_in[17];

    float* xbuf = (float*)d_out;

    __half *xn, *qkv, *o, *m, *wt;
    float *bqkv;
    cudaGetSymbolAddress((void**)&xn,   g_xn);
    cudaGetSymbolAddress((void**)&qkv,  g_qkv);
    cudaGetSymbolAddress((void**)&o,    g_o);
    cudaGetSymbolAddress((void**)&m,    g_m);
    cudaGetSymbolAddress((void**)&wt,   g_wt);
    cudaGetSymbolAddress((void**)&bqkv, g_bqkv);

    cudaFuncSetAttribute(mg_gemm<1>, cudaFuncAttributeMaxDynamicSharedMemorySize, MG_SMEM);
    cudaFuncSetAttribute(mg_gemm<2>, cudaFuncAttributeMaxDynamicSharedMemorySize, MG_SMEM);
    cudaFuncSetAttribute(mg_gemm<3>, cudaFuncAttributeMaxDynamicSharedMemorySize, MG_SMEM);

    cudaMemcpyAsync(xbuf, x_in, (size_t)NTOK * DIM * sizeof(float),
                    cudaMemcpyDeviceToDevice);

    // Weight transform, all layers batched via blockIdx.z
    wtrans_kernel<<<dim3(16, 16, NLAYER), 256>>>(Wq,  wt + WOFF_Q,  512, 512);
    wtrans_kernel<<<dim3(32, 16, NLAYER), 256>>>(Wkv, wt + WOFF_KV, 512, 1024);
    wtrans_kernel<<<dim3(16, 16, NLAYER), 256>>>(Wo,  wt + WOFF_O,  512, 512);
    wtrans_kernel<<<dim3(64, 16, NLAYER), 256>>>(W1,  wt + WOFF_W1, 512, 2048);
    wtrans_kernel<<<dim3(16, 64, NLAYER), 256>>>(W2,  wt + WOFF_W2, 2048, 512);
    bcat_kernel<<<dim3(NLAYER, 3), 512>>>(bq, bkv, bqkv);

    dim3 gLN(NTOK / 8), bLN(256);
    dim3 gAttn(NHEAD, 64, BATCH), bAttn(256);

    for (int l = 0; l < NLAYER; l++) {
        size_t lw = (size_t)l * WLAYER;
        const float* bov  = bo  + (size_t)l * DIM;
        const float* tab  = rel_table + (size_t)l * 225 * NHEAD;
        const float* b1v  = b1  + (size_t)l * 4 * DIM;
        const float* b2v  = b2  + (size_t)l * DIM;

        ln_kernel<<<gLN, bLN>>>(xbuf, ln1_g + (size_t)l*DIM, ln1_b + (size_t)l*DIM, xn);
        // Fused Q+KV GEMM: N=1536 over adjacent [Wq|Wkv] transposed block
        mg_gemm<3><<<dim3(12, 256), 256, MG_SMEM>>>(
            xn, wt + lw + WOFF_Q, bqkv + (size_t)l * 1536, nullptr,
            nullptr, qkv, NTOK, 1536, 512);
        attn_kernel<<<gAttn, bAttn>>>(qkv, rel_index, tab, o);
        mg_gemm<2><<<dim3(4, 256), 256, MG_SMEM>>>(
            o, wt + lw + WOFF_O, bov, xbuf, xbuf, nullptr, NTOK, 512, 512);
        ln_kernel<<<gLN, bLN>>>(xbuf, ln2_g + (size_t)l*DIM, ln2_b + (size_t)l*DIM, xn);
        mg_gemm<1><<<dim3(16, 256), 256, MG_SMEM>>>(
            xn, wt + lw + WOFF_W1, b1v, nullptr, nullptr, m, NTOK, 2048, 512);
        mg_gemm<2><<<dim3(4, 256), 256, MG_SMEM>>>(
            m, wt + lw + WOFF_W2, b2v, xbuf, xbuf, nullptr, NTOK, 512, 2048);
    }
}